// round 14
// baseline (speedup 1.0000x reference)
#include <cuda_runtime.h>
#include <cstdint>

typedef unsigned long long ULL;

// Problem constants: B=128, T=1024, H=128, D=64, L=3
#define BB   128
#define TT   1024
#define HH   128
#define G4   512
#define MROWS (BB*TT)
#define CHUNK 128
#define NCHUNK 8

// Scratch (device globals: allocation-rule-safe)
__device__ float g_xg[(size_t)MROWS * G4];    // 256 MB (recycled per layer-chunk)
__device__ float g_y [(size_t)MROWS * HH];    // 64 MB  (recycled per layer-chunk)
__device__ float g_whl[3][512 * 128 * 2];     // per-layer Wih as interleaved (hi,lo)

// ---------------------------------------------------------------------------
// helpers
// ---------------------------------------------------------------------------
__device__ __forceinline__ void fma2(ULL& acc, ULL a, ULL b) {
    asm("fma.rn.f32x2 %0, %1, %2, %0;" : "+l"(acc) : "l"(a), "l"(b));
}
__device__ __forceinline__ void upk2(ULL v, float& lo, float& hi) {
    asm("mov.b64 {%0, %1}, %2;" : "=f"(lo), "=f"(hi) : "l"(v));
}
__device__ __forceinline__ float tanhapx(float x) {
    float y; asm("tanh.approx.f32 %0, %1;" : "=f"(y) : "f"(x)); return y;
}
__device__ __forceinline__ float sigapx(float x) {
    return fmaf(tanhapx(0.5f * x), 0.5f, 0.5f);
}
__device__ __forceinline__ uint32_t smem_u32(const void* p) {
    uint32_t a;
    asm("{ .reg .u64 t; cvta.to.shared.u64 t, %1; cvt.u32.u64 %0, t; }"
        : "=r"(a) : "l"(p));
    return a;
}
__device__ __forceinline__ uint32_t mapa_u32(uint32_t a, uint32_t rank) {
    uint32_t r;
    asm("mapa.shared::cluster.u32 %0, %1, %2;" : "=r"(r) : "r"(a), "r"(rank));
    return r;
}
__device__ __forceinline__ uint32_t f2tf32(float v) {
    uint32_t r; asm("cvt.rna.tf32.f32 %0, %1;" : "=r"(r) : "f"(v)); return r;
}
__device__ __forceinline__ void mma_tf32(float& c0, float& c1, float& c2, float& c3,
                                         uint32_t a0, uint32_t a1, uint32_t a2, uint32_t a3,
                                         uint32_t b0, uint32_t b1) {
    asm("mma.sync.aligned.m16n8k8.row.col.f32.tf32.tf32.f32 "
        "{%0,%1,%2,%3},{%4,%5,%6,%7},{%8,%9},{%0,%1,%2,%3};"
        : "+f"(c0), "+f"(c1), "+f"(c2), "+f"(c3)
        : "r"(a0), "r"(a1), "r"(a2), "r"(a3), "r"(b0), "r"(b1));
}

// ---------------------------------------------------------------------------
// init: copy h0,c0 -> state arrays
// ---------------------------------------------------------------------------
__global__ void init_state(const float* __restrict__ h0,
                           const float* __restrict__ c0,
                           float* __restrict__ hN, float* __restrict__ cN)
{
    int i = blockIdx.x * blockDim.x + threadIdx.x;
    if (i < 3 * BB * HH) { hN[i] = h0[i]; cN[i] = c0[i]; }
}

// ---------------------------------------------------------------------------
// w_conv: W[512*K] -> g_whl[l] interleaved (hi, lo)
// ---------------------------------------------------------------------------
__global__ void w_conv(const float* __restrict__ W, int l, int n)
{
    int i = blockIdx.x * blockDim.x + threadIdx.x;
    if (i < n) {
        float v = W[i];
        float h = __uint_as_float(f2tf32(v));
        g_whl[l][2 * i]     = h;
        g_whl[l][2 * i + 1] = v - h;
    }
}

// ---------------------------------------------------------------------------
// 3xTF32 tensor-core GEMM (verbatim from R13 — passing).
// ---------------------------------------------------------------------------
template<int K>
__global__ __launch_bounds__(256, 2)
void xg_tf32(const float* __restrict__ Aext, int use_gy, int layer,
             const float* __restrict__ bih,
             const float* __restrict__ bhh,
             int t0, int lg)
{
    __shared__ float Ahl[2][128][9][2];
    __shared__ float Bhl[2][128][9][2];

    const float* A   = use_gy ? (const float*)g_y : Aext;
    const float* Whl = g_whl[layer];

    const int tid  = threadIdx.x;
    const int lane = tid & 31;
    const int warp = tid >> 5;
    const int wm   = warp & 1;
    const int wn   = warp >> 1;
    const int gq   = lane >> 2;
    const int tq   = lane & 3;

    const int m0 = ((blockIdx.y >> lg) * TT) + t0 +
                   ((blockIdx.y & ((1 << lg) - 1)) * 128);
    const int n0 = blockIdx.x * 128;

    const int srow = tid >> 1;
    const int skk  = (tid & 1) * 4;

    float acc[4][4][4];
#pragma unroll
    for (int i = 0; i < 4; i++)
#pragma unroll
        for (int j = 0; j < 4; j++)
#pragma unroll
            for (int q = 0; q < 4; q++) acc[i][j][q] = 0.f;

    float bias[4][2];
#pragma unroll
    for (int nt = 0; nt < 4; nt++) {
        int col = n0 + wn * 32 + nt * 8 + tq * 2;
        bias[nt][0] = bih[col] + bhh[col];
        bias[nt][1] = bih[col + 1] + bhh[col + 1];
    }

    {
        float4 av = *(const float4*)(A + (size_t)(m0 + srow) * K + skk);
        const float aa[4] = {av.x, av.y, av.z, av.w};
#pragma unroll
        for (int j = 0; j < 4; j++) {
            float h = __uint_as_float(f2tf32(aa[j]));
            *(float2*)&Ahl[0][srow][skk + j][0] = make_float2(h, aa[j] - h);
        }
        const float4* wv = (const float4*)(Whl + ((size_t)(n0 + srow) * K + skk) * 2);
        float4 w0 = wv[0], w1 = wv[1];
        *(float2*)&Bhl[0][srow][skk + 0][0] = make_float2(w0.x, w0.y);
        *(float2*)&Bhl[0][srow][skk + 1][0] = make_float2(w0.z, w0.w);
        *(float2*)&Bhl[0][srow][skk + 2][0] = make_float2(w1.x, w1.y);
        *(float2*)&Bhl[0][srow][skk + 3][0] = make_float2(w1.z, w1.w);
    }
    __syncthreads();

    const int NC = K / 8;
    for (int c = 0; c < NC; ++c) {
        const int cur = c & 1, nxt = cur ^ 1;
        float aa[4];
        float4 w0, w1;
        if (c + 1 < NC) {
            float4 av = *(const float4*)(A + (size_t)(m0 + srow) * K + (c + 1) * 8 + skk);
            aa[0] = av.x; aa[1] = av.y; aa[2] = av.z; aa[3] = av.w;
            const float4* wv = (const float4*)(Whl +
                ((size_t)(n0 + srow) * K + (c + 1) * 8 + skk) * 2);
            w0 = wv[0]; w1 = wv[1];
        }

        uint32_t bh[4][2], bl[4][2];
#pragma unroll
        for (int nt = 0; nt < 4; nt++) {
            int nr = wn * 32 + nt * 8 + gq;
            float2 v0 = *(const float2*)&Bhl[cur][nr][tq][0];
            float2 v1 = *(const float2*)&Bhl[cur][nr][tq + 4][0];
            bh[nt][0] = __float_as_uint(v0.x); bl[nt][0] = __float_as_uint(v0.y);
            bh[nt][1] = __float_as_uint(v1.x); bl[nt][1] = __float_as_uint(v1.y);
        }
#pragma unroll
        for (int mt = 0; mt < 4; mt++) {
            int mr = wm * 64 + mt * 16 + gq;
            float2 u0 = *(const float2*)&Ahl[cur][mr][tq][0];
            float2 u1 = *(const float2*)&Ahl[cur][mr + 8][tq][0];
            float2 u2 = *(const float2*)&Ahl[cur][mr][tq + 4][0];
            float2 u3 = *(const float2*)&Ahl[cur][mr + 8][tq + 4][0];
            uint32_t ah0 = __float_as_uint(u0.x), al0 = __float_as_uint(u0.y);
            uint32_t ah1 = __float_as_uint(u1.x), al1 = __float_as_uint(u1.y);
            uint32_t ah2 = __float_as_uint(u2.x), al2 = __float_as_uint(u2.y);
            uint32_t ah3 = __float_as_uint(u3.x), al3 = __float_as_uint(u3.y);
#pragma unroll
            for (int nt = 0; nt < 4; nt++) {
                float* cc = acc[mt][nt];
                mma_tf32(cc[0], cc[1], cc[2], cc[3],
                         ah0, ah1, ah2, ah3, bh[nt][0], bh[nt][1]);
                mma_tf32(cc[0], cc[1], cc[2], cc[3],
                         ah0, ah1, ah2, ah3, bl[nt][0], bl[nt][1]);
                mma_tf32(cc[0], cc[1], cc[2], cc[3],
                         al0, al1, al2, al3, bh[nt][0], bh[nt][1]);
            }
        }

        if (c + 1 < NC) {
#pragma unroll
            for (int j = 0; j < 4; j++) {
                float h = __uint_as_float(f2tf32(aa[j]));
                *(float2*)&Ahl[nxt][srow][skk + j][0] = make_float2(h, aa[j] - h);
            }
            *(float2*)&Bhl[nxt][srow][skk + 0][0] = make_float2(w0.x, w0.y);
            *(float2*)&Bhl[nxt][srow][skk + 1][0] = make_float2(w0.z, w0.w);
            *(float2*)&Bhl[nxt][srow][skk + 2][0] = make_float2(w1.x, w1.y);
            *(float2*)&Bhl[nxt][srow][skk + 3][0] = make_float2(w1.z, w1.w);
            __syncthreads();
        }
    }

#pragma unroll
    for (int mt = 0; mt < 4; mt++) {
        int row0 = m0 + wm * 64 + mt * 16 + gq;
#pragma unroll
        for (int nt = 0; nt < 4; nt++) {
            int col = n0 + wn * 32 + nt * 8 + tq * 2;
            float* cc = acc[mt][nt];
            *(float2*)(g_xg + (size_t)row0 * G4 + col) =
                make_float2(cc[0] + bias[nt][0], cc[1] + bias[nt][1]);
            *(float2*)(g_xg + (size_t)(row0 + 8) * G4 + col) =
                make_float2(cc[2] + bias[nt][0], cc[3] + bias[nt][1]);
        }
    }
}

// ---------------------------------------------------------------------------
// Recurrent chunk v14: 8 batch rows / cluster (16 clusters = 32 CTAs per job)
// so 3 layer-jobs fit in one wall (96 CTAs). Sync skeleton = R10 verbatim.
// Gate threads (256, peer-k group) each handle TWO units:
//   unit0 = (row = jp&3,     n = r*64 + (jp>>2))
//   unit1 = (row = (jp&3)+4, same n)
// ---------------------------------------------------------------------------
__global__ __launch_bounds__(512, 1) __cluster_dims__(2, 1, 1)
void lstm_rec14(const float* __restrict__ whh0,
                const float* __restrict__ whh1,
                const float* __restrict__ whh2,
                float* __restrict__ hN, float* __restrict__ cN,
                int4 lsel, int4 tsel)
{
    __shared__ __align__(16) float hbuf[2][8][132];  // [parity][row][n]
    __shared__ __align__(16) float land[2][8][68];   // [parity][row][nn]
    __shared__ __align__(16) float pre[2][256][8];   // [kh][jp][row]
    __shared__ __align__(8)  ULL   bar;

    const int lc = blockIdx.y;
    const int l  = (lc == 0) ? lsel.x : (lc == 1) ? lsel.y : lsel.z;
    const int t0 = (lc == 0) ? tsel.x : (lc == 1) ? tsel.y : tsel.z;
    const float* whh = (l == 0) ? whh0 : (l == 1) ? whh1 : whh2;
    float* hstate = hN + l * BB * HH;
    float* cstate = cN + l * BB * HH;

    const int tid = threadIdx.x;
    const int r   = blockIdx.x & 1;
    const int b0  = (blockIdx.x >> 1) * 8;

    const int kh = tid >> 8;
    const int jp = tid & 255;
    const int g  = jp >> 6;
    const int nn = jp & 63;

    uint32_t bar_addr = smem_u32(&bar);
    uint32_t peer_bar = mapa_u32(bar_addr, (uint32_t)(r ^ 1));

    if (tid == 0) {
        asm volatile("mbarrier.init.shared.b64 [%0], %1;"
                     :: "r"(bar_addr), "r"(8) : "memory");
    }
    // load h state: 8 rows x 128
#pragma unroll
    for (int i = tid; i < 8 * HH; i += 512)
        hbuf[1][i >> 7][i & 127] = hstate[(b0 + (i >> 7)) * HH + (i & 127)];

    const int row_w = g * 128 + r * 64 + nn;
    ULL w2[32];
    const ULL* wp = (const ULL*)(whh + (size_t)row_w * HH + kh * 64);
#pragma unroll
    for (int i = 0; i < 32; i++) w2[i] = wp[i];

    const bool is_gate = (kh == (r ^ 1));
    const int row_a = jp & 3;            // unit rows: row_a and row_a+4
    const int nn_g  = jp >> 2;           // [0,64)
    const int n_g   = r * 64 + nn_g;

    float cs[2] = {0.f, 0.f}, hl[2] = {0.f, 0.f};
    const float* px[2] = {nullptr, nullptr};
    float*       py[2] = {nullptr, nullptr};
    uint32_t pl[2][2];                   // [unit][parity]
    float xc[2][4], xn[2][4];
    if (is_gate) {
#pragma unroll
        for (int u = 0; u < 2; u++) {
            int row = row_a + u * 4;
            cs[u] = cstate[(b0 + row) * HH + n_g];
            px[u] = g_xg + ((size_t)(b0 + row) * TT) * G4 + n_g;
            py[u] = g_y  + ((size_t)(b0 + row) * TT) * HH + n_g;
            pl[u][0] = mapa_u32(smem_u32(&land[0][row][nn_g]), (uint32_t)(r ^ 1));
            pl[u][1] = mapa_u32(smem_u32(&land[1][row][nn_g]), (uint32_t)(r ^ 1));
            const float* p0 = px[u] + (size_t)t0 * G4;
#pragma unroll
            for (int q = 0; q < 4; q++) {
                xc[u][q] = p0[q * 128];
                xn[u][q] = p0[G4 + q * 128];
            }
        }
    }

    __syncthreads();
    asm volatile("barrier.cluster.arrive.aligned;" ::: "memory");
    asm volatile("barrier.cluster.wait.aligned;"   ::: "memory");

    for (int s = 0; s < CHUNK; ++s) {
        const int t  = t0 + s;
        const int pr = (s + 1) & 1;
        const int pw = s & 1;

        // matvec: all warps, 8 batch rows, this thread's 64-k half
        float s8[8];
#pragma unroll
        for (int rr = 0; rr < 8; rr += 2) {
            ULL a0 = 0, a1 = 0, c0_ = 0, c1_ = 0;
            const ulonglong2* hA = (const ulonglong2*)&hbuf[pr][rr][kh * 64];
            const ulonglong2* hB = (const ulonglong2*)&hbuf[pr][rr + 1][kh * 64];
#pragma unroll
            for (int i = 0; i < 16; i++) {
                ulonglong2 uA = hA[i], uB = hB[i];
                fma2(a0,  w2[2 * i],     uA.x);
                fma2(a1,  w2[2 * i + 1], uA.y);
                fma2(c0_, w2[2 * i],     uB.x);
                fma2(c1_, w2[2 * i + 1], uB.y);
            }
            float x0, x1, x2, x3;
            upk2(a0, x0, x1); upk2(a1, x2, x3);
            s8[rr] = (x0 + x1) + (x2 + x3);
            upk2(c0_, x0, x1); upk2(c1_, x2, x3);
            s8[rr + 1] = (x0 + x1) + (x2 + x3);
        }
        *(float4*)&pre[kh][jp][0] = make_float4(s8[0], s8[1], s8[2], s8[3]);
        *(float4*)&pre[kh][jp][4] = make_float4(s8[4], s8[5], s8[6], s8[7]);
        __syncthreads();                          // pre[] ready

        if (is_gate) {
#pragma unroll
            for (int u = 0; u < 2; u++) {
                int row = row_a + u * 4;
                float pi = pre[0][      nn_g][row] + pre[1][      nn_g][row];
                float pf = pre[0][ 64 + nn_g][row] + pre[1][ 64 + nn_g][row];
                float pg = pre[0][128 + nn_g][row] + pre[1][128 + nn_g][row];
                float po = pre[0][192 + nn_g][row] + pre[1][192 + nn_g][row];
                float iv = sigapx(pi + xc[u][0]);
                float fv = sigapx(pf + xc[u][1]);
                float gv = tanhapx(pg + xc[u][2]);
                float ov = sigapx(po + xc[u][3]);
                float cc = fv * cs[u] + iv * gv;
                cs[u] = cc;
                float hh = ov * tanhapx(cc);
                hl[u] = hh;
                asm volatile("st.shared::cluster.f32 [%0], %1;"
                             :: "r"(pl[u][pw]), "f"(hh) : "memory");
                hbuf[pw][row][n_g] = hh;
            }
            __syncwarp();
            if ((tid & 31) == 0) {
                asm volatile("mbarrier.arrive.release.cluster.shared::cluster.b64 _, [%0];"
                             :: "r"(peer_bar) : "memory");
            }
            {
                unsigned par = (unsigned)(s & 1);
                asm volatile(
                    "{\n\t"
                    ".reg .pred P1;\n\t"
                    "WLP%=:\n\t"
                    "mbarrier.try_wait.parity.acquire.cluster.shared::cta.b64 P1, [%0], %1, 0x989680;\n\t"
                    "@!P1 bra WLP%=;\n\t"
                    "}"
                    :: "r"(bar_addr), "r"(par) : "memory");
            }
#pragma unroll
            for (int u = 0; u < 2; u++) {
                int row = row_a + u * 4;
                hbuf[pw][row][((r ^ 1) * 64) + nn_g] = land[pw][row][nn_g];
            }
        }
        __syncthreads();                          // hbuf fully ready for s+1

        // off the critical path
        if (is_gate) {
#pragma unroll
            for (int u = 0; u < 2; u++) {
                py[u][(size_t)t * HH] = hl[u];
                float xf0 = 0, xf1 = 0, xf2 = 0, xf3 = 0;
                if (s + 2 < CHUNK) {
                    const float* p2 = px[u] + (size_t)(t + 2) * G4;
                    xf0 = p2[0]; xf1 = p2[128]; xf2 = p2[256]; xf3 = p2[384];
                }
                xc[u][0] = xn[u][0]; xc[u][1] = xn[u][1];
                xc[u][2] = xn[u][2]; xc[u][3] = xn[u][3];
                xn[u][0] = xf0; xn[u][1] = xf1; xn[u][2] = xf2; xn[u][3] = xf3;
            }
        }
    }

    if (is_gate) {
#pragma unroll
        for (int u = 0; u < 2; u++) {
            int row = row_a + u * 4;
            hstate[(b0 + row) * HH + n_g] = hl[u];
            cstate[(b0 + row) * HH + n_g] = cs[u];
        }
    }
    asm volatile("barrier.cluster.arrive.aligned;" ::: "memory");
    asm volatile("barrier.cluster.wait.aligned;"   ::: "memory");
}

// ---------------------------------------------------------------------------
// Output projection
// ---------------------------------------------------------------------------
__global__ __launch_bounds__(256)
void proj_kernel(const float* __restrict__ wout,
                 const float* __restrict__ bout,
                 float* __restrict__ out)
{
    int gwarp = (blockIdx.x * blockDim.x + threadIdx.x) >> 5;
    int lane  = threadIdx.x & 31;
    if (gwarp >= MROWS) return;
    float4 yv = ((const float4*)(g_y + (size_t)gwarp * HH))[lane];
    float4 wv = ((const float4*)wout)[lane];
    float s = yv.x * wv.x + yv.y * wv.y + yv.z * wv.z + yv.w * wv.w;
#pragma unroll
    for (int o = 16; o; o >>= 1) s += __shfl_xor_sync(0xFFFFFFFFu, s, o);
    if (lane == 0) out[gwarp] = fmaxf(s + bout[0], 0.f);
}

// ---------------------------------------------------------------------------
// Schedule: 10 walls, <=3 jobs (96 CTAs) per wall.
//  w_k: (0,k)(1,k-1)(2,k-2) for valid c in [0,8)
// gemm(1,c) after w_c; gemm(2,c) after w_{c+1}.
// ---------------------------------------------------------------------------
extern "C" void kernel_launch(void* const* d_in, const int* in_sizes, int n_in,
                              void* d_out, int out_size)
{
    const float* x    = (const float*)d_in[0];
    const float* h0   = (const float*)d_in[1];
    const float* c0   = (const float*)d_in[2];
    const float* Wih[3] = {(const float*)d_in[3], (const float*)d_in[7],  (const float*)d_in[11]};
    const float* Whh[3] = {(const float*)d_in[4], (const float*)d_in[8],  (const float*)d_in[12]};
    const float* bih[3] = {(const float*)d_in[5], (const float*)d_in[9],  (const float*)d_in[13]};
    const float* bhh[3] = {(const float*)d_in[6], (const float*)d_in[10], (const float*)d_in[14]};
    const float* Wout = (const float*)d_in[15];
    const float* bout = (const float*)d_in[16];

    float* out = (float*)d_out;           // [B*T]
    float* hN  = out + MROWS;             // [3,B,H]
    float* cN  = hN + 3 * BB * HH;

    init_state<<<(3 * BB * HH + 511) / 512, 512>>>(h0, c0, hN, cN);
    w_conv<<<(512 * 64 + 255) / 256, 256>>>(Wih[0], 0, 512 * 64);
    w_conv<<<(512 * 128 + 255) / 256, 256>>>(Wih[1], 1, 512 * 128);
    w_conv<<<(512 * 128 + 255) / 256, 256>>>(Wih[2], 2, 512 * 128);

    // layer-0 xg, full T
    xg_tf32<64><<<dim3(4, 1024), 256>>>(x, 0, 0, bih[0], bhh[0], 0, 3);

    const int C = CHUNK;
    auto gemm = [&](int l, int cc) {
        xg_tf32<128><<<dim3(4, 128), 256>>>(nullptr, 1, l, bih[l], bhh[l],
                                            cc * C, 0);
    };

    for (int k = 0; k <= 9; k++) {
        // rec wall k: jobs (l, c=k-l), 0 <= c < 8
        int ls[3], ts[3], n = 0;
        for (int l = 0; l < 3; l++) {
            int cc = k - l;
            if (cc >= 0 && cc < NCHUNK) { ls[n] = l; ts[n] = cc * C; n++; }
        }
        if (n > 0) {
            int4 lsel = make_int4(ls[0], n > 1 ? ls[1] : 0, n > 2 ? ls[2] : 0, 0);
            int4 tsel = make_int4(ts[0], n > 1 ? ts[1] : 0, n > 2 ? ts[2] : 0, 0);
            lstm_rec14<<<dim3(32, n), 512>>>(Whh[0], Whh[1], Whh[2],
                                             hN, cN, lsel, tsel);
        }
        // gemms feeding future walls: gemm(1,k) after wall k ran (0,k);
        // gemm(2,k-1) after wall k ran (1,k-1)
        if (k < NCHUNK)          gemm(1, k);
        if (k >= 1 && k - 1 < NCHUNK) gemm(2, k - 1);
    }

    proj_kernel<<<MROWS / 8, 256>>>(Wout, bout, out);
}

// round 15
// speedup vs baseline: 1.5219x; 1.5219x over previous
#include <cuda_runtime.h>
#include <cstdint>

typedef unsigned long long ULL;

// Problem constants: B=128, T=1024, H=128, D=64, L=3
#define BB   128
#define TT   1024
#define HH   128
#define G4   512
#define MROWS (BB*TT)
#define CHUNK 128
#define NCHUNK 8

// Scratch (device globals: allocation-rule-safe)
__device__ float g_xg[(size_t)MROWS * G4];    // 256 MB (recycled per layer-chunk)
__device__ float g_y [(size_t)MROWS * HH];    // 64 MB  (recycled per layer-chunk)
__device__ float g_whl[3][512 * 128 * 2];     // per-layer Wih as interleaved (hi,lo)

// ---------------------------------------------------------------------------
// helpers
// ---------------------------------------------------------------------------
__device__ __forceinline__ void fma2(ULL& acc, ULL a, ULL b) {
    asm("fma.rn.f32x2 %0, %1, %2, %0;" : "+l"(acc) : "l"(a), "l"(b));
}
__device__ __forceinline__ void upk2(ULL v, float& lo, float& hi) {
    asm("mov.b64 {%0, %1}, %2;" : "=f"(lo), "=f"(hi) : "l"(v));
}
__device__ __forceinline__ float tanhapx(float x) {
    float y; asm("tanh.approx.f32 %0, %1;" : "=f"(y) : "f"(x)); return y;
}
__device__ __forceinline__ float sigapx(float x) {
    return fmaf(tanhapx(0.5f * x), 0.5f, 0.5f);
}
__device__ __forceinline__ uint32_t smem_u32(const void* p) {
    uint32_t a;
    asm("{ .reg .u64 t; cvta.to.shared.u64 t, %1; cvt.u32.u64 %0, t; }"
        : "=r"(a) : "l"(p));
    return a;
}
__device__ __forceinline__ uint32_t mapa_u32(uint32_t a, uint32_t rank) {
    uint32_t r;
    asm("mapa.shared::cluster.u32 %0, %1, %2;" : "=r"(r) : "r"(a), "r"(rank));
    return r;
}
__device__ __forceinline__ uint32_t f2tf32(float v) {
    uint32_t r; asm("cvt.rna.tf32.f32 %0, %1;" : "=r"(r) : "f"(v)); return r;
}
__device__ __forceinline__ void mma_tf32(float& c0, float& c1, float& c2, float& c3,
                                         uint32_t a0, uint32_t a1, uint32_t a2, uint32_t a3,
                                         uint32_t b0, uint32_t b1) {
    asm("mma.sync.aligned.m16n8k8.row.col.f32.tf32.tf32.f32 "
        "{%0,%1,%2,%3},{%4,%5,%6,%7},{%8,%9},{%0,%1,%2,%3};"
        : "+f"(c0), "+f"(c1), "+f"(c2), "+f"(c3)
        : "r"(a0), "r"(a1), "r"(a2), "r"(a3), "r"(b0), "r"(b1));
}

// ---------------------------------------------------------------------------
// init: copy h0,c0 -> state arrays
// ---------------------------------------------------------------------------
__global__ void init_state(const float* __restrict__ h0,
                           const float* __restrict__ c0,
                           float* __restrict__ hN, float* __restrict__ cN)
{
    int i = blockIdx.x * blockDim.x + threadIdx.x;
    if (i < 3 * BB * HH) { hN[i] = h0[i]; cN[i] = c0[i]; }
}

// ---------------------------------------------------------------------------
// w_conv: W[512*K] -> g_whl[l] interleaved (hi, lo)
// ---------------------------------------------------------------------------
__global__ void w_conv(const float* __restrict__ W, int l, int n)
{
    int i = blockIdx.x * blockDim.x + threadIdx.x;
    if (i < n) {
        float v = W[i];
        float h = __uint_as_float(f2tf32(v));
        g_whl[l][2 * i]     = h;
        g_whl[l][2 * i + 1] = v - h;
    }
}

// ---------------------------------------------------------------------------
// 3xTF32 tensor-core GEMM (verbatim from R13 — passing).
// ---------------------------------------------------------------------------
template<int K>
__global__ __launch_bounds__(256, 2)
void xg_tf32(const float* __restrict__ Aext, int use_gy, int layer,
             const float* __restrict__ bih,
             const float* __restrict__ bhh,
             int t0, int lg)
{
    __shared__ float Ahl[2][128][9][2];
    __shared__ float Bhl[2][128][9][2];

    const float* A   = use_gy ? (const float*)g_y : Aext;
    const float* Whl = g_whl[layer];

    const int tid  = threadIdx.x;
    const int lane = tid & 31;
    const int warp = tid >> 5;
    const int wm   = warp & 1;
    const int wn   = warp >> 1;
    const int gq   = lane >> 2;
    const int tq   = lane & 3;

    const int m0 = ((blockIdx.y >> lg) * TT) + t0 +
                   ((blockIdx.y & ((1 << lg) - 1)) * 128);
    const int n0 = blockIdx.x * 128;

    const int srow = tid >> 1;
    const int skk  = (tid & 1) * 4;

    float acc[4][4][4];
#pragma unroll
    for (int i = 0; i < 4; i++)
#pragma unroll
        for (int j = 0; j < 4; j++)
#pragma unroll
            for (int q = 0; q < 4; q++) acc[i][j][q] = 0.f;

    float bias[4][2];
#pragma unroll
    for (int nt = 0; nt < 4; nt++) {
        int col = n0 + wn * 32 + nt * 8 + tq * 2;
        bias[nt][0] = bih[col] + bhh[col];
        bias[nt][1] = bih[col + 1] + bhh[col + 1];
    }

    {
        float4 av = *(const float4*)(A + (size_t)(m0 + srow) * K + skk);
        const float aa[4] = {av.x, av.y, av.z, av.w};
#pragma unroll
        for (int j = 0; j < 4; j++) {
            float h = __uint_as_float(f2tf32(aa[j]));
            *(float2*)&Ahl[0][srow][skk + j][0] = make_float2(h, aa[j] - h);
        }
        const float4* wv = (const float4*)(Whl + ((size_t)(n0 + srow) * K + skk) * 2);
        float4 w0 = wv[0], w1 = wv[1];
        *(float2*)&Bhl[0][srow][skk + 0][0] = make_float2(w0.x, w0.y);
        *(float2*)&Bhl[0][srow][skk + 1][0] = make_float2(w0.z, w0.w);
        *(float2*)&Bhl[0][srow][skk + 2][0] = make_float2(w1.x, w1.y);
        *(float2*)&Bhl[0][srow][skk + 3][0] = make_float2(w1.z, w1.w);
    }
    __syncthreads();

    const int NC = K / 8;
    for (int c = 0; c < NC; ++c) {
        const int cur = c & 1, nxt = cur ^ 1;
        float aa[4];
        float4 w0, w1;
        if (c + 1 < NC) {
            float4 av = *(const float4*)(A + (size_t)(m0 + srow) * K + (c + 1) * 8 + skk);
            aa[0] = av.x; aa[1] = av.y; aa[2] = av.z; aa[3] = av.w;
            const float4* wv = (const float4*)(Whl +
                ((size_t)(n0 + srow) * K + (c + 1) * 8 + skk) * 2);
            w0 = wv[0]; w1 = wv[1];
        }

        uint32_t bh[4][2], bl[4][2];
#pragma unroll
        for (int nt = 0; nt < 4; nt++) {
            int nr = wn * 32 + nt * 8 + gq;
            float2 v0 = *(const float2*)&Bhl[cur][nr][tq][0];
            float2 v1 = *(const float2*)&Bhl[cur][nr][tq + 4][0];
            bh[nt][0] = __float_as_uint(v0.x); bl[nt][0] = __float_as_uint(v0.y);
            bh[nt][1] = __float_as_uint(v1.x); bl[nt][1] = __float_as_uint(v1.y);
        }
#pragma unroll
        for (int mt = 0; mt < 4; mt++) {
            int mr = wm * 64 + mt * 16 + gq;
            float2 u0 = *(const float2*)&Ahl[cur][mr][tq][0];
            float2 u1 = *(const float2*)&Ahl[cur][mr + 8][tq][0];
            float2 u2 = *(const float2*)&Ahl[cur][mr][tq + 4][0];
            float2 u3 = *(const float2*)&Ahl[cur][mr + 8][tq + 4][0];
            uint32_t ah0 = __float_as_uint(u0.x), al0 = __float_as_uint(u0.y);
            uint32_t ah1 = __float_as_uint(u1.x), al1 = __float_as_uint(u1.y);
            uint32_t ah2 = __float_as_uint(u2.x), al2 = __float_as_uint(u2.y);
            uint32_t ah3 = __float_as_uint(u3.x), al3 = __float_as_uint(u3.y);
#pragma unroll
            for (int nt = 0; nt < 4; nt++) {
                float* cc = acc[mt][nt];
                mma_tf32(cc[0], cc[1], cc[2], cc[3],
                         ah0, ah1, ah2, ah3, bh[nt][0], bh[nt][1]);
                mma_tf32(cc[0], cc[1], cc[2], cc[3],
                         ah0, ah1, ah2, ah3, bl[nt][0], bl[nt][1]);
                mma_tf32(cc[0], cc[1], cc[2], cc[3],
                         al0, al1, al2, al3, bh[nt][0], bh[nt][1]);
            }
        }

        if (c + 1 < NC) {
#pragma unroll
            for (int j = 0; j < 4; j++) {
                float h = __uint_as_float(f2tf32(aa[j]));
                *(float2*)&Ahl[nxt][srow][skk + j][0] = make_float2(h, aa[j] - h);
            }
            *(float2*)&Bhl[nxt][srow][skk + 0][0] = make_float2(w0.x, w0.y);
            *(float2*)&Bhl[nxt][srow][skk + 1][0] = make_float2(w0.z, w0.w);
            *(float2*)&Bhl[nxt][srow][skk + 2][0] = make_float2(w1.x, w1.y);
            *(float2*)&Bhl[nxt][srow][skk + 3][0] = make_float2(w1.z, w1.w);
            __syncthreads();
        }
    }

#pragma unroll
    for (int mt = 0; mt < 4; mt++) {
        int row0 = m0 + wm * 64 + mt * 16 + gq;
#pragma unroll
        for (int nt = 0; nt < 4; nt++) {
            int col = n0 + wn * 32 + nt * 8 + tq * 2;
            float* cc = acc[mt][nt];
            *(float2*)(g_xg + (size_t)row0 * G4 + col) =
                make_float2(cc[0] + bias[nt][0], cc[1] + bias[nt][1]);
            *(float2*)(g_xg + (size_t)(row0 + 8) * G4 + col) =
                make_float2(cc[2] + bias[nt][0], cc[3] + bias[nt][1]);
        }
    }
}

// ---------------------------------------------------------------------------
// Recurrent chunk (verbatim from R13 — passing, 4 batch rows / cluster).
// ---------------------------------------------------------------------------
__global__ __launch_bounds__(512, 1) __cluster_dims__(2, 1, 1)
void lstm_rec10(const float* __restrict__ whh0,
                const float* __restrict__ whh1,
                const float* __restrict__ whh2,
                float* __restrict__ hN, float* __restrict__ cN,
                int4 lsel, int4 tsel)
{
    __shared__ __align__(16) float hbuf[2][4][132];
    __shared__ __align__(16) float land[2][4][68];
    __shared__ __align__(16) float pre[2][256][4];
    __shared__ __align__(8)  ULL   bar;

    const int lc = blockIdx.y;
    const int l  = (lc == 0) ? lsel.x : (lc == 1) ? lsel.y : lsel.z;
    const int t0 = (lc == 0) ? tsel.x : (lc == 1) ? tsel.y : tsel.z;
    const float* whh = (l == 0) ? whh0 : (l == 1) ? whh1 : whh2;
    float* hstate = hN + l * BB * HH;
    float* cstate = cN + l * BB * HH;

    const int tid = threadIdx.x;
    const int r   = blockIdx.x & 1;
    const int b0  = (blockIdx.x >> 1) * 4;

    const int kh = tid >> 8;
    const int jp = tid & 255;
    const int g  = jp >> 6;
    const int nn = jp & 63;

    uint32_t bar_addr = smem_u32(&bar);
    uint32_t peer_bar = mapa_u32(bar_addr, (uint32_t)(r ^ 1));

    if (tid == 0) {
        asm volatile("mbarrier.init.shared.b64 [%0], %1;"
                     :: "r"(bar_addr), "r"(8) : "memory");
    }
    {
        int row = tid >> 7, n = tid & 127;
        hbuf[1][row][n] = hstate[(b0 + row) * HH + n];
    }

    const int row_w = g * 128 + r * 64 + nn;
    ULL w2[32];
    const ULL* wp = (const ULL*)(whh + (size_t)row_w * HH + kh * 64);
#pragma unroll
    for (int i = 0; i < 32; i++) w2[i] = wp[i];

    const bool is_gate = (kh == (r ^ 1));
    const int row_g = jp & 3;
    const int nn_g  = jp >> 2;
    const int n_g   = r * 64 + nn_g;

    float c = 0.f, hlast = 0.f;
    const float* px = g_xg + ((size_t)(b0 + row_g) * TT) * G4 + n_g;
    float*       py = g_y  + ((size_t)(b0 + row_g) * TT) * HH + n_g;
    uint32_t pl0 = 0, pl1 = 0;
    float xc0=0,xc1=0,xc2=0,xc3=0, xn0=0,xn1=0,xn2=0,xn3=0;
    if (is_gate) {
        c   = cstate[(b0 + row_g) * HH + n_g];
        pl0 = mapa_u32(smem_u32(&land[0][row_g][nn_g]), (uint32_t)(r ^ 1));
        pl1 = mapa_u32(smem_u32(&land[1][row_g][nn_g]), (uint32_t)(r ^ 1));
        const float* p0 = px + (size_t)t0 * G4;
        xc0 = p0[0];        xc1 = p0[128];        xc2 = p0[256];        xc3 = p0[384];
        xn0 = p0[G4 + 0];   xn1 = p0[G4 + 128];   xn2 = p0[G4 + 256];   xn3 = p0[G4 + 384];
    }

    __syncthreads();
    asm volatile("barrier.cluster.arrive.aligned;" ::: "memory");
    asm volatile("barrier.cluster.wait.aligned;"   ::: "memory");

    for (int s = 0; s < CHUNK; ++s) {
        const int t  = t0 + s;
        const int pr = (s + 1) & 1;
        const int pw = s & 1;

        float s4[4];
#pragma unroll
        for (int rr = 0; rr < 4; rr += 2) {
            ULL a0 = 0, a1 = 0, c0_ = 0, c1_ = 0;
            const ulonglong2* hA = (const ulonglong2*)&hbuf[pr][rr][kh * 64];
            const ulonglong2* hB = (const ulonglong2*)&hbuf[pr][rr + 1][kh * 64];
#pragma unroll
            for (int i = 0; i < 16; i++) {
                ulonglong2 uA = hA[i], uB = hB[i];
                fma2(a0,  w2[2 * i],     uA.x);
                fma2(a1,  w2[2 * i + 1], uA.y);
                fma2(c0_, w2[2 * i],     uB.x);
                fma2(c1_, w2[2 * i + 1], uB.y);
            }
            float x0, x1, x2, x3;
            upk2(a0, x0, x1); upk2(a1, x2, x3);
            s4[rr] = (x0 + x1) + (x2 + x3);
            upk2(c0_, x0, x1); upk2(c1_, x2, x3);
            s4[rr + 1] = (x0 + x1) + (x2 + x3);
        }
        *(float4*)&pre[kh][jp][0] = make_float4(s4[0], s4[1], s4[2], s4[3]);
        __syncthreads();

        if (is_gate) {
            float pi = pre[0][      nn_g][row_g] + pre[1][      nn_g][row_g];
            float pf = pre[0][ 64 + nn_g][row_g] + pre[1][ 64 + nn_g][row_g];
            float pg = pre[0][128 + nn_g][row_g] + pre[1][128 + nn_g][row_g];
            float po = pre[0][192 + nn_g][row_g] + pre[1][192 + nn_g][row_g];
            float iv = sigapx(pi + xc0);
            float fv = sigapx(pf + xc1);
            float gv = tanhapx(pg + xc2);
            float ov = sigapx(po + xc3);
            c = fv * c + iv * gv;
            float hh = ov * tanhapx(c);
            hlast = hh;
            uint32_t pa = pw ? pl1 : pl0;
            asm volatile("st.shared::cluster.f32 [%0], %1;"
                         :: "r"(pa), "f"(hh) : "memory");
            hbuf[pw][row_g][n_g] = hh;
            __syncwarp();
            if ((tid & 31) == 0) {
                asm volatile("mbarrier.arrive.release.cluster.shared::cluster.b64 _, [%0];"
                             :: "r"(peer_bar) : "memory");
            }
            {
                unsigned par = (unsigned)(s & 1);
                asm volatile(
                    "{\n\t"
                    ".reg .pred P1;\n\t"
                    "WLP%=:\n\t"
                    "mbarrier.try_wait.parity.acquire.cluster.shared::cta.b64 P1, [%0], %1, 0x989680;\n\t"
                    "@!P1 bra WLP%=;\n\t"
                    "}"
                    :: "r"(bar_addr), "r"(par) : "memory");
            }
            hbuf[pw][row_g][((r ^ 1) * 64) + nn_g] = land[pw][row_g][nn_g];
        }
        __syncthreads();

        if (is_gate) {
            py[(size_t)t * HH] = hlast;
            float xf0 = 0, xf1 = 0, xf2 = 0, xf3 = 0;
            if (s + 2 < CHUNK) {
                const float* p2 = px + (size_t)(t + 2) * G4;
                xf0 = p2[0]; xf1 = p2[128]; xf2 = p2[256]; xf3 = p2[384];
            }
            xc0 = xn0; xc1 = xn1; xc2 = xn2; xc3 = xn3;
            xn0 = xf0; xn1 = xf1; xn2 = xf2; xn3 = xf3;
        }
    }

    if (is_gate) {
        hstate[(b0 + row_g) * HH + n_g] = hlast;
        cstate[(b0 + row_g) * HH + n_g] = c;
    }
    asm volatile("barrier.cluster.arrive.aligned;" ::: "memory");
    asm volatile("barrier.cluster.wait.aligned;"   ::: "memory");
}

// ---------------------------------------------------------------------------
// Output projection
// ---------------------------------------------------------------------------
__global__ __launch_bounds__(256)
void proj_kernel(const float* __restrict__ wout,
                 const float* __restrict__ bout,
                 float* __restrict__ out)
{
    int gwarp = (blockIdx.x * blockDim.x + threadIdx.x) >> 5;
    int lane  = threadIdx.x & 31;
    if (gwarp >= MROWS) return;
    float4 yv = ((const float4*)(g_y + (size_t)gwarp * HH))[lane];
    float4 wv = ((const float4*)wout)[lane];
    float s = yv.x * wv.x + yv.y * wv.y + yv.z * wv.z + yv.w * wv.w;
#pragma unroll
    for (int o = 16; o; o >>= 1) s += __shfl_xor_sync(0xFFFFFFFFu, s, o);
    if (lane == 0) out[gwarp] = fmaxf(s + bout[0], 0.f);
}

// ---------------------------------------------------------------------------
// R13 schedule + side-stream overlap. Walls (13, main stream):
//  w0:(0,0) w1:(0,1)(1,0) w2:(0,2)(1,1) w3:(0,3)(2,0) w4:(0,4)(1,2)
//  w5:(0,5)(2,1) w6:(0,6)(1,3) w7:(0,7)(2,2) w8:(1,4)(2,3) w9:(1,5)(2,4)
//  w10:(1,6)(2,5) w11:(1,7)(2,6) w12:(2,7)
// Serial (gap-0) gemms on main: (1,0) after w0, (1,1) after w1,
//  (2,4) after w8, (2,5) after w9, (2,6) after w10, (2,7) after w11.
// Overlapped on s2 (wait producer-wall event, signal consumer-wall event):
//  g0(1..7) after w_conv(0); (2,0) P=w1,C=w3; (1,2) P=w2,C=w4; (2,1) P=w2,C=w5;
//  (1,3) P=w3,C=w6; (2,2) P=w4,C=w7; (1,4) P=w4,C=w8; (1,5) P=w5,C=w9;
//  (2,3) P=w6,C=w8; (1,6) P=w6,C=w10; (1,7) P=w7,C=w11.
// Hazards: gemm(l,c) touches only regions of chunk c; every wall between its
// producer and consumer contains no chunk-c job (schedule property), and the
// producer/consumer events order all region reads/writes.
// ---------------------------------------------------------------------------
extern "C" void kernel_launch(void* const* d_in, const int* in_sizes, int n_in,
                              void* d_out, int out_size)
{
    const float* x    = (const float*)d_in[0];
    const float* h0   = (const float*)d_in[1];
    const float* c0   = (const float*)d_in[2];
    const float* Wih[3] = {(const float*)d_in[3], (const float*)d_in[7],  (const float*)d_in[11]};
    const float* Whh[3] = {(const float*)d_in[4], (const float*)d_in[8],  (const float*)d_in[12]};
    const float* bih[3] = {(const float*)d_in[5], (const float*)d_in[9],  (const float*)d_in[13]};
    const float* bhh[3] = {(const float*)d_in[6], (const float*)d_in[10], (const float*)d_in[14]};
    const float* Wout = (const float*)d_in[15];
    const float* bout = (const float*)d_in[16];

    float* out = (float*)d_out;
    float* hN  = out + MROWS;
    float* cN  = hN + 3 * BB * HH;

    // lazy one-time stream/event creation (host-side resources only; created
    // on the first, uncaptured call; reused verbatim in the captured call)
    static cudaStream_t s2 = nullptr;
    static cudaEvent_t evPre, evW[8], evG0[8], evC[13];
    if (!s2) {
        cudaStreamCreateWithFlags(&s2, cudaStreamNonBlocking);
        cudaEventCreateWithFlags(&evPre, cudaEventDisableTiming);
        for (int i = 0; i < 8; i++) {
            cudaEventCreateWithFlags(&evW[i], cudaEventDisableTiming);
            cudaEventCreateWithFlags(&evG0[i], cudaEventDisableTiming);
        }
        for (int i = 0; i < 13; i++)
            cudaEventCreateWithFlags(&evC[i], cudaEventDisableTiming);
    }

    const int C = CHUNK;
    auto rec1 = [&](int l0_, int t0_) {
        lstm_rec10<<<dim3(64, 1), 512>>>(Whh[0], Whh[1], Whh[2], hN, cN,
                                         make_int4(l0_, 0, 0, 0),
                                         make_int4(t0_, 0, 0, 0));
    };
    auto rec2 = [&](int la, int ta, int lb, int tb) {
        lstm_rec10<<<dim3(64, 2), 512>>>(Whh[0], Whh[1], Whh[2], hN, cN,
                                         make_int4(la, lb, 0, 0),
                                         make_int4(ta, tb, 0, 0));
    };
    auto gemmM = [&](int l, int cc) {   // main stream
        xg_tf32<128><<<dim3(4, 128), 256>>>(nullptr, 1, l, bih[l], bhh[l],
                                            cc * C, 0);
    };
    auto gemmS = [&](int l, int cc) {   // side stream
        xg_tf32<128><<<dim3(4, 128), 256, 0, s2>>>(nullptr, 1, l, bih[l],
                                                   bhh[l], cc * C, 0);
    };
    auto gemm0S = [&](int cc) {         // layer-0 chunk on side stream
        xg_tf32<64><<<dim3(4, 128), 256, 0, s2>>>(x, 0, 0, bih[0], bhh[0],
                                                  cc * C, 0);
    };

    // prologue (main)
    init_state<<<(3 * BB * HH + 511) / 512, 512>>>(h0, c0, hN, cN);
    w_conv<<<(512 * 64 + 255) / 256, 256>>>(Wih[0], 0, 512 * 64);
    w_conv<<<(512 * 128 + 255) / 256, 256>>>(Wih[1], 1, 512 * 128);
    w_conv<<<(512 * 128 + 255) / 256, 256>>>(Wih[2], 2, 512 * 128);
    xg_tf32<64><<<dim3(4, 128), 256>>>(x, 0, 0, bih[0], bhh[0], 0, 0); // g0(0)
    cudaEventRecord(evPre, 0);

    // side stream program (in-order): g0(1..7), then wall-gated gemms
    cudaStreamWaitEvent(s2, evPre, 0);
    for (int cc = 1; cc < 8; cc++) { gemm0S(cc); cudaEventRecord(evG0[cc], s2); }

    // ---- walls ----
    rec1(0, 0);                                   // w0
    gemmM(1, 0);                                  // serial (gap 0)
    cudaStreamWaitEvent(0, evG0[1], 0);
    rec2(0, 1 * C, 1, 0 * C);                     // w1
    cudaEventRecord(evW[1], 0);
    gemmM(1, 1);                                  // serial (gap 0)

    cudaStreamWaitEvent(s2, evW[1], 0);
    gemmS(2, 0); cudaEventRecord(evC[3], s2);

    cudaStreamWaitEvent(0, evG0[2], 0);
    rec2(0, 2 * C, 1, 1 * C);                     // w2
    cudaEventRecord(evW[2], 0);

    cudaStreamWaitEvent(s2, evW[2], 0);
    gemmS(1, 2); cudaEventRecord(evC[4], s2);
    gemmS(2, 1); cudaEventRecord(evC[5], s2);

    cudaStreamWaitEvent(0, evG0[3], 0);
    cudaStreamWaitEvent(0, evC[3], 0);
    rec2(0, 3 * C, 2, 0 * C);                     // w3
    cudaEventRecord(evW[3], 0);

    cudaStreamWaitEvent(s2, evW[3], 0);
    gemmS(1, 3); cudaEventRecord(evC[6], s2);

    cudaStreamWaitEvent(0, evG0[4], 0);
    cudaStreamWaitEvent(0, evC[4], 0);
    rec2(0, 4 * C, 1, 2 * C);                     // w4
    cudaEventRecord(evW[4], 0);

    cudaStreamWaitEvent(s2, evW[4], 0);
    gemmS(2, 2); cudaEventRecord(evC[7], s2);
    gemmS(1, 4);                                  // covered by evC[8] later

    cudaStreamWaitEvent(0, evG0[5], 0);
    cudaStreamWaitEvent(0, evC[5], 0);
    rec2(0, 5 * C, 2, 1 * C);                     // w5
    cudaEventRecord(evW[5], 0);

    cudaStreamWaitEvent(s2, evW[5], 0);
    gemmS(1, 5); cudaEventRecord(evC[9], s2);

    cudaStreamWaitEvent(0, evG0[6], 0);
    cudaStreamWaitEvent(0, evC[6], 0);
    rec2(0, 6 * C, 1, 3 * C);                     // w6
    cudaEventRecord(evW[6], 0);

    cudaStreamWaitEvent(s2, evW[6], 0);
    gemmS(2, 3); cudaEventRecord(evC[8], s2);     // also covers g(1,4)
    gemmS(1, 6); cudaEventRecord(evC[10], s2);

    cudaStreamWaitEvent(0, evG0[7], 0);
    cudaStreamWaitEvent(0, evC[7], 0);
    rec2(0, 7 * C, 2, 2 * C);                     // w7
    cudaEventRecord(evW[7], 0);

    cudaStreamWaitEvent(s2, evW[7], 0);
    gemmS(1, 7); cudaEventRecord(evC[11], s2);

    cudaStreamWaitEvent(0, evC[8], 0);
    rec2(1, 4 * C, 2, 3 * C);                     // w8
    gemmM(2, 4);                                  // serial (gap 0)

    cudaStreamWaitEvent(0, evC[9], 0);
    rec2(1, 5 * C, 2, 4 * C);                     // w9
    gemmM(2, 5);

    cudaStreamWaitEvent(0, evC[10], 0);
    rec2(1, 6 * C, 2, 5 * C);                     // w10
    gemmM(2, 6);

    cudaStreamWaitEvent(0, evC[11], 0);
    rec2(1, 7 * C, 2, 6 * C);                     // w11
    gemmM(2, 7);

    rec1(2, 7 * C);                               // w12

    proj_kernel<<<MROWS / 8, 256>>>(Wout, bout, out);
}